// round 6
// baseline (speedup 1.0000x reference)
#include <cuda_runtime.h>
#include <cuda_bf16.h>
#include <math.h>

// SimDiff: right[f,i] = cos(x[f,i], x[f+iv, i+1])      (i < tpf-1)
//          down [f,i] = cos(x[f,i], x[f+iv, i+width])  (i < tpf-width)
// else -1. Output: [right | down], each frames*tpf f32.
//
// LTS-cap regime (12.2 TB/s L2 plateau across R2/R3/R5 regardless of occ).
// This kernel reduces L2 read traffic with GUARANTEED smem reuse:
//  - block owns a 64-anchor band and chained relations (f -> f+iv, f+iv -> f+2iv)
//  - frame f+iv staged once in smem: right-targets + down-targets of rel A AND
//    anchors of rel B; frame f+2iv staged once: targets of rel B
//  - D chunked at 64 floats: fill -> bar -> compute, accumulators in regs
// Global loads/block/chunk ~ 64 (rel-A anchors, LDG) + 257 slot fills
// (~241 distinct) for 384 uses -> ~0.63x traffic -> cap-time ~26us.

#define EPSN 1e-8f
#define SPAN 64
#define NTHREADS 512
#define CH 64                    // floats per chunk per token
#define NSLOT 257                // 4 segments * 64 + 1 extra (token j0, frame f+iv)
#define SMEM_BYTES (NSLOT * CH * 4)   // 65792

extern __shared__ float sm[];    // [NSLOT][CH]

__global__ void __launch_bounds__(NTHREADS, 2) simdiff_chain_kernel(
    const float* __restrict__ x,
    const int* __restrict__ p_frames,
    const int* __restrict__ p_height,
    const int* __restrict__ p_width,
    const int* __restrict__ p_interval,
    float* __restrict__ out,
    int total, int D)
{
    const int width  = *p_width;
    const int height = *p_height;
    const int frames = *p_frames;
    const int iv     = *p_interval;
    const int tpf    = width * height;

    const int nb     = (tpf + SPAN - 1) / SPAN;
    // chain index c -> (qe = c/iv, r = c%iv); anchor frame f = 2*qe*iv + r.
    const int nchain = ((frames + 2 * iv - 1) / (2 * iv)) * iv;
    const int npair  = nb * nchain;

    const int tid  = threadIdx.x;
    const int wid  = tid >> 5;          // 0..15
    const int lane = tid & 31;
    const int l2   = lane * 2;

    float* __restrict__ outR = out;
    float* __restrict__ outD = out + total;

    for (int p = blockIdx.x; p < npair; p += gridDim.x) {
        const int cidx = p / nb;
        const int band = p - cidx * nb;
        const int j0   = band * SPAN;

        const int r  = cidx % iv;
        const int qe = cidx / iv;
        const int f  = 2 * qe * iv + r;
        if (f >= frames) continue;

        const int fT1 = f + iv;          // rel-A targets / rel-B anchors
        const int fT2 = f + 2 * iv;      // rel-B targets
        const int fT1c = fT1 < frames ? fT1 : frames - 1;
        const int fT2c = fT2 < frames ? fT2 : frames - 1;
        const bool relA = (fT1 < frames);
        const bool relB = (fT2 < frames);

        // This warp: rel A (wid<8, anchors frame f) or rel B (anchors frame fT1).
        const bool isB   = (wid >= 8);
        const int  aq0   = j0 + (wid & 7) * 8;
        const int  segoff = isB ? 128 : 0;
        const int  fa    = isB ? fT1c : f;

        float na[8], d1[8], n1[8], d2[8], n2[8];
#pragma unroll
        for (int q = 0; q < 8; q++) {
            na[q] = 0.0f; d1[q] = 0.0f; n1[q] = 0.0f; d2[q] = 0.0f; n2[q] = 0.0f;
        }

        for (int c = 0; c < D; c += CH) {
            __syncthreads();   // previous chunk's readers done before refill
            // ---- fill: 257 slots x 16 float4 ----
            for (int idx = tid; idx < NSLOT * (CH / 4); idx += NTHREADS) {
                const int slot = idx >> 4;
                const int off  = idx & 15;
                int t, fr;
                if (slot < 64)       { t = j0 + 1 + slot;             fr = fT1c; }
                else if (slot < 128) { t = j0 + width + (slot - 64);  fr = fT1c; }
                else if (slot < 192) { t = j0 + 1 + (slot - 128);     fr = fT2c; }
                else if (slot < 256) { t = j0 + width + (slot - 192); fr = fT2c; }
                else                 { t = j0;                        fr = fT1c; }
                if (t >= tpf) t = tpf - 1;
                const float4 v = reinterpret_cast<const float4*>(
                    x + ((size_t)fr * tpf + t) * D + c)[off];
                reinterpret_cast<float4*>(sm + slot * CH)[off] = v;
            }
            __syncthreads();
            // ---- compute: 8 anchors per warp ----
#pragma unroll
            for (int q = 0; q < 8; q++) {
                const int a  = aq0 + q;                  // in [j0, j0+63]
                const int aL = a < tpf ? a : tpf - 1;
                float2 av;
                if (!isB) {
                    av = *reinterpret_cast<const float2*>(
                        x + ((size_t)f * tpf + aL) * D + c + l2);
                } else {
                    const int as = (a == j0) ? 256 : (a - j0 - 1);
                    av = *reinterpret_cast<const float2*>(sm + as * CH + l2);
                }
                const int rs = segoff + (a - j0);
                const int ds = (a + width <= j0 + SPAN)
                                 ? segoff + (a + width - j0 - 1)
                                 : segoff + 64 + (a - j0);
                const float2 bv = *reinterpret_cast<const float2*>(sm + rs * CH + l2);
                const float2 cv = *reinterpret_cast<const float2*>(sm + ds * CH + l2);
                na[q] = fmaf(av.x, av.x, na[q]); na[q] = fmaf(av.y, av.y, na[q]);
                d1[q] = fmaf(av.x, bv.x, d1[q]); d1[q] = fmaf(av.y, bv.y, d1[q]);
                n1[q] = fmaf(bv.x, bv.x, n1[q]); n1[q] = fmaf(bv.y, bv.y, n1[q]);
                d2[q] = fmaf(av.x, cv.x, d2[q]); d2[q] = fmaf(av.y, cv.y, d2[q]);
                n2[q] = fmaf(cv.x, cv.x, n2[q]); n2[q] = fmaf(cv.y, cv.y, n2[q]);
            }
        }

        // ---- reduce + write ----
#pragma unroll
        for (int q = 0; q < 8; q++) {
            float vna = na[q], vd1 = d1[q], vn1 = n1[q], vd2 = d2[q], vn2 = n2[q];
#pragma unroll
            for (int off = 16; off > 0; off >>= 1) {
                vna += __shfl_xor_sync(0xFFFFFFFFu, vna, off);
                vd1 += __shfl_xor_sync(0xFFFFFFFFu, vd1, off);
                vn1 += __shfl_xor_sync(0xFFFFFFFFu, vn1, off);
                vd2 += __shfl_xor_sync(0xFFFFFFFFu, vd2, off);
                vn2 += __shfl_xor_sync(0xFFFFFFFFu, vn2, off);
            }
            if (lane == 0) {
                const int a = aq0 + q;
                if (a < tpf) {
                    const bool rv = isB ? relB : relA;    // relation validity
                    const bool fw = isB ? (fT1 < frames) : true;  // anchor frame exists
                    if (fw) {
                        const bool vr = rv && (a < tpf - 1);
                        const bool vd = rv && (a < tpf - width);
                        const int  t  = fa * tpf + a;
                        const float nA = fmaxf(sqrtf(vna), EPSN);
                        outR[t] = vr ? vd1 / (nA * fmaxf(sqrtf(vn1), EPSN)) : -1.0f;
                        outD[t] = vd ? vd2 / (nA * fmaxf(sqrtf(vn2), EPSN)) : -1.0f;
                    }
                }
            }
        }
    }
}

// Generic fallback for arbitrary D (scalar loads, one warp per token).
__global__ void __launch_bounds__(256) simdiff_generic_kernel(
    const float* __restrict__ x,
    const int* __restrict__ p_frames,
    const int* __restrict__ p_height,
    const int* __restrict__ p_width,
    const int* __restrict__ p_interval,
    float* __restrict__ out,
    int total, int D)
{
    const int gwarp = (blockIdx.x * blockDim.x + threadIdx.x) >> 5;
    const int lane  = threadIdx.x & 31;
    if (gwarp >= total) return;

    const int width    = *p_width;
    const int height   = *p_height;
    const int frames   = *p_frames;
    const int interval = *p_interval;
    const int tpf      = width * height;

    const int f = gwarp / tpf;
    const int i = gwarp - f * tpf;

    float* __restrict__ outR = out;
    float* __restrict__ outD = out + total;

    const bool vf = (f + interval) < frames;
    if (!vf) {
        if (lane == 0) { outR[gwarp] = -1.0f; outD[gwarp] = -1.0f; }
        return;
    }
    const bool vr = (i < tpf - 1);
    const bool vd = (i < tpf - width);

    const size_t bframe = (size_t)(f + interval) * tpf + i;
    const size_t i1 = vr ? (bframe + 1)     : bframe;
    const size_t i2 = vd ? (bframe + width) : bframe;

    const float* a = x + (size_t)gwarp * D;
    const float* b = x + i1 * D;
    const float* c = x + i2 * D;

    float na = 0.0f, d1 = 0.0f, n1 = 0.0f, d2 = 0.0f, n2 = 0.0f;
    for (int k = lane; k < D; k += 32) {
        float av = a[k], bv = b[k], cv = c[k];
        na = fmaf(av, av, na);
        d1 = fmaf(av, bv, d1); n1 = fmaf(bv, bv, n1);
        d2 = fmaf(av, cv, d2); n2 = fmaf(cv, cv, n2);
    }

#pragma unroll
    for (int off = 16; off > 0; off >>= 1) {
        na += __shfl_xor_sync(0xFFFFFFFFu, na, off);
        d1 += __shfl_xor_sync(0xFFFFFFFFu, d1, off);
        n1 += __shfl_xor_sync(0xFFFFFFFFu, n1, off);
        d2 += __shfl_xor_sync(0xFFFFFFFFu, d2, off);
        n2 += __shfl_xor_sync(0xFFFFFFFFu, n2, off);
    }

    if (lane == 0) {
        const float nA = fmaxf(sqrtf(na), EPSN);
        outR[gwarp] = vr ? d1 / (nA * fmaxf(sqrtf(n1), EPSN)) : -1.0f;
        outD[gwarp] = vd ? d2 / (nA * fmaxf(sqrtf(n2), EPSN)) : -1.0f;
    }
}

extern "C" void kernel_launch(void* const* d_in, const int* in_sizes, int n_in,
                              void* d_out, int out_size) {
    const float* x        = (const float*)d_in[0];
    const int* p_frames   = (const int*)d_in[1];
    const int* p_height   = (const int*)d_in[2];
    const int* p_width    = (const int*)d_in[3];
    const int* p_interval = (const int*)d_in[4];
    float* out = (float*)d_out;

    const int total = out_size / 2;            // frames * tpf
    const int D     = in_sizes[0] / total;     // hidden dim

    if (D >= 64 && (D % 64) == 0) {
        static bool attr_set = false;
        if (!attr_set) {
            cudaFuncSetAttribute(simdiff_chain_kernel,
                                 cudaFuncAttributeMaxDynamicSharedMemorySize,
                                 SMEM_BYTES);
            attr_set = true;
        }
        // Useful blocks ~ (frames/2) * ceil(tpf/64) ~ total/128; grid-stride
        // covers any shape. Extra blocks exit immediately.
        const int blocks = (total + 127) / 128 + 96;
        simdiff_chain_kernel<<<blocks, NTHREADS, SMEM_BYTES>>>(
            x, p_frames, p_height, p_width, p_interval, out, total, D);
    } else {
        const int blocks = (total + 7) / 8;
        simdiff_generic_kernel<<<blocks, 256>>>(
            x, p_frames, p_height, p_width, p_interval, out, total, D);
    }
}

// round 7
// speedup vs baseline: 2.2094x; 2.2094x over previous
#include <cuda_runtime.h>
#include <cuda_bf16.h>
#include <math.h>

// SimDiff: right[f,i] = cos(x[f,i], x[f+iv, i+1])      (i < tpf-1)
//          down [f,i] = cos(x[f,i], x[f+iv, i+width])  (i < tpf-width)
// else -1. Output: [right | down], each frames*tpf f32.
//
// LTS-cap regime (~12 TB/s L2 read plateau). Register-only traffic reduction
// via DIAGONAL CHAINING: the right-target of (f,i) IS the anchor of
// (f+iv,i+1). A warp walks S=4 chain steps; per step it loads only the new
// right-target b (becomes next anchor by register copy) and the down-target c.
// Norm chaining: n[k+1] is both step-k right-denominator and step-(k+1)
// anchor norm. L2 reads/token = 2 + 1/S = 2.25 (vs 3.0 naive), FMA -20%.
// No smem, no barriers, addresses = base + small precomputed int offsets.

#define EPSN 1e-8f
#define SEG 4   // chain steps (anchor tokens) per warp segment

template <int NPL>  // D = NPL * 128 floats; chunk = 1 float4 per lane
__global__ void __launch_bounds__(256, 5) simdiff_diag_kernel(
    const float* __restrict__ x,
    const int* __restrict__ p_frames,
    const int* __restrict__ p_height,
    const int* __restrict__ p_width,
    const int* __restrict__ p_interval,
    float* __restrict__ out,
    int total)
{
    const int width  = *p_width;
    const int height = *p_height;
    const int frames = *p_frames;
    const int iv     = *p_interval;
    const int tpf    = width * height;

    // Chains: step (f += iv, i += 1). Starts: f0 < iv (any i0), or i0 == 0.
    const int nch_a = iv * tpf;                         // starts with f0 < iv
    const int nch_b = frames > iv ? frames - iv : 0;    // starts with i0 = 0
    const int nch   = nch_a + nch_b;
    const int maxL  = min((frames + iv - 1) / iv, tpf);
    const int msg   = (maxL + SEG - 1) / SEG;           // segments per chain
    const long nseg = (long)nch * msg;

    const int lane = threadIdx.x & 31;
    const long warps_total = (long)gridDim.x * (blockDim.x >> 5);
    const long gwarp0 = ((long)blockIdx.x * blockDim.x + threadIdx.x) >> 5;

    float* __restrict__ outR = out;
    float* __restrict__ outD = out + total;
    const int vstride4 = NPL * 32;          // float4s per token vector
    const int dtok = iv * tpf + 1;          // token stride per chain step
    const int ctok = iv * tpf + width;      // down-target offset from anchor

    for (long g = gwarp0; g < nseg; g += warps_total) {
        const int chain = (int)(g / msg);
        const int seg   = (int)(g - (long)chain * msg);

        int f0, i0;
        if (chain < nch_a) { f0 = chain % iv; i0 = chain / iv; }
        else               { f0 = iv + (chain - nch_a); i0 = 0; }

        const int L  = min((frames - f0 + iv - 1) / iv, tpf - i0);
        const int k0 = seg * SEG;
        if (k0 >= L) continue;
        const int nout = min(SEG, L - k0);  // anchors owned by this segment

        const int fb = f0 + k0 * iv;
        const int ib = i0 + k0;
        const long t0 = (long)fb * tpf + ib;

        // Per-step float4 offsets relative to t0's vector (0 if OOB -> safe
        // duplicate load of t0; results discarded via vr/vd).
        int offB[SEG], offC[SEG];
#pragma unroll
        for (int k = 0; k < SEG; k++) {
            const long tb = t0 + (long)(k + 1) * dtok;
            const long tc = t0 + (long)k * dtok + ctok;
            offB[k] = (tb < total) ? (int)((tb - t0) * vstride4) : 0;
            offC[k] = (tc < total) ? (int)((tc - t0) * vstride4) : 0;
        }

        const float4* __restrict__ base4 =
            reinterpret_cast<const float4*>(x) + t0 * vstride4 + lane;

        float n[SEG + 1], d1[SEG], d2[SEG], n2[SEG];
#pragma unroll
        for (int k = 0; k < SEG; k++) { d1[k] = 0.f; d2[k] = 0.f; n2[k] = 0.f; n[k] = 0.f; }
        n[SEG] = 0.f;

#pragma unroll
        for (int ch = 0; ch < NPL; ch++) {
            const float4* __restrict__ p = base4 + ch * 32;
            float4 a = p[0];
            n[0] = fmaf(a.x, a.x, n[0]); n[0] = fmaf(a.y, a.y, n[0]);
            n[0] = fmaf(a.z, a.z, n[0]); n[0] = fmaf(a.w, a.w, n[0]);
#pragma unroll
            for (int k = 0; k < SEG; k++) {
                const float4 b = p[offB[k]];
                const float4 c = p[offC[k]];
                d1[k] = fmaf(a.x, b.x, d1[k]); d1[k] = fmaf(a.y, b.y, d1[k]);
                d1[k] = fmaf(a.z, b.z, d1[k]); d1[k] = fmaf(a.w, b.w, d1[k]);
                n[k+1] = fmaf(b.x, b.x, n[k+1]); n[k+1] = fmaf(b.y, b.y, n[k+1]);
                n[k+1] = fmaf(b.z, b.z, n[k+1]); n[k+1] = fmaf(b.w, b.w, n[k+1]);
                d2[k] = fmaf(a.x, c.x, d2[k]); d2[k] = fmaf(a.y, c.y, d2[k]);
                d2[k] = fmaf(a.z, c.z, d2[k]); d2[k] = fmaf(a.w, c.w, d2[k]);
                n2[k] = fmaf(c.x, c.x, n2[k]); n2[k] = fmaf(c.y, c.y, n2[k]);
                n2[k] = fmaf(c.z, c.z, n2[k]); n2[k] = fmaf(c.w, c.w, n2[k]);
                a = b;  // chain: target becomes next anchor
            }
        }

        // Warp-reduce all accumulators.
#pragma unroll
        for (int off = 16; off > 0; off >>= 1) {
#pragma unroll
            for (int k = 0; k < SEG + 1; k++)
                n[k] += __shfl_xor_sync(0xFFFFFFFFu, n[k], off);
#pragma unroll
            for (int k = 0; k < SEG; k++) {
                d1[k] += __shfl_xor_sync(0xFFFFFFFFu, d1[k], off);
                d2[k] += __shfl_xor_sync(0xFFFFFFFFu, d2[k], off);
                n2[k] += __shfl_xor_sync(0xFFFFFFFFu, n2[k], off);
            }
        }

        if (lane == 0) {
#pragma unroll
            for (int k = 0; k < SEG; k++) {
                if (k < nout) {
                    const int kk = k0 + k;
                    const int fA = f0 + kk * iv;
                    const int iA = i0 + kk;
                    const int t  = fA * tpf + iA;
                    const bool fv = (fA + iv) < frames;
                    const bool vr = fv && (iA + 1 < tpf);
                    const bool vd = fv && (iA < tpf - width);
                    const float nA = fmaxf(sqrtf(n[k]), EPSN);
                    outR[t] = vr ? d1[k] / (nA * fmaxf(sqrtf(n[k+1]), EPSN)) : -1.0f;
                    outD[t] = vd ? d2[k] / (nA * fmaxf(sqrtf(n2[k]), EPSN)) : -1.0f;
                }
            }
        }
    }
}

// Generic fallback for arbitrary D (scalar loads, one warp per token).
__global__ void __launch_bounds__(256) simdiff_generic_kernel(
    const float* __restrict__ x,
    const int* __restrict__ p_frames,
    const int* __restrict__ p_height,
    const int* __restrict__ p_width,
    const int* __restrict__ p_interval,
    float* __restrict__ out,
    int total, int D)
{
    const int gwarp = (blockIdx.x * blockDim.x + threadIdx.x) >> 5;
    const int lane  = threadIdx.x & 31;
    if (gwarp >= total) return;

    const int width    = *p_width;
    const int height   = *p_height;
    const int frames   = *p_frames;
    const int interval = *p_interval;
    const int tpf      = width * height;

    const int f = gwarp / tpf;
    const int i = gwarp - f * tpf;

    float* __restrict__ outR = out;
    float* __restrict__ outD = out + total;

    const bool vf = (f + interval) < frames;
    if (!vf) {
        if (lane == 0) { outR[gwarp] = -1.0f; outD[gwarp] = -1.0f; }
        return;
    }
    const bool vr = (i < tpf - 1);
    const bool vd = (i < tpf - width);

    const size_t bframe = (size_t)(f + interval) * tpf + i;
    const size_t i1 = vr ? (bframe + 1)     : bframe;
    const size_t i2 = vd ? (bframe + width) : bframe;

    const float* a = x + (size_t)gwarp * D;
    const float* b = x + i1 * D;
    const float* c = x + i2 * D;

    float na = 0.0f, d1 = 0.0f, n1 = 0.0f, d2 = 0.0f, n2 = 0.0f;
    for (int k = lane; k < D; k += 32) {
        float av = a[k], bv = b[k], cv = c[k];
        na = fmaf(av, av, na);
        d1 = fmaf(av, bv, d1); n1 = fmaf(bv, bv, n1);
        d2 = fmaf(av, cv, d2); n2 = fmaf(cv, cv, n2);
    }

#pragma unroll
    for (int off = 16; off > 0; off >>= 1) {
        na += __shfl_xor_sync(0xFFFFFFFFu, na, off);
        d1 += __shfl_xor_sync(0xFFFFFFFFu, d1, off);
        n1 += __shfl_xor_sync(0xFFFFFFFFu, n1, off);
        d2 += __shfl_xor_sync(0xFFFFFFFFu, d2, off);
        n2 += __shfl_xor_sync(0xFFFFFFFFu, n2, off);
    }

    if (lane == 0) {
        const float nA = fmaxf(sqrtf(na), EPSN);
        outR[gwarp] = vr ? d1 / (nA * fmaxf(sqrtf(n1), EPSN)) : -1.0f;
        outD[gwarp] = vd ? d2 / (nA * fmaxf(sqrtf(n2), EPSN)) : -1.0f;
    }
}

extern "C" void kernel_launch(void* const* d_in, const int* in_sizes, int n_in,
                              void* d_out, int out_size) {
    const float* x        = (const float*)d_in[0];
    const int* p_frames   = (const int*)d_in[1];
    const int* p_height   = (const int*)d_in[2];
    const int* p_width    = (const int*)d_in[3];
    const int* p_interval = (const int*)d_in[4];
    float* out = (float*)d_out;

    const int total = out_size / 2;            // frames * tpf
    const int D     = in_sizes[0] / total;     // hidden dim

    if (D == 1152 || D == 1024 || D == 1280) {
        // ~total/SEG segment-warps needed (+ chain-edge extras); grid-stride
        // covers the remainder, dead warps exit fast.
        const int blocks = total / (8 * SEG) + 160;
        if (D == 1152) {
            simdiff_diag_kernel<9><<<blocks, 256>>>(
                x, p_frames, p_height, p_width, p_interval, out, total);
        } else if (D == 1024) {
            simdiff_diag_kernel<8><<<blocks, 256>>>(
                x, p_frames, p_height, p_width, p_interval, out, total);
        } else {
            simdiff_diag_kernel<10><<<blocks, 256>>>(
                x, p_frames, p_height, p_width, p_interval, out, total);
        }
    } else {
        const int blocks = (total + 7) / 8;
        simdiff_generic_kernel<<<blocks, 256>>>(
            x, p_frames, p_height, p_width, p_interval, out, total, D);
    }
}

// round 8
// speedup vs baseline: 2.5197x; 1.1404x over previous
#include <cuda_runtime.h>
#include <cuda_bf16.h>
#include <math.h>

// SimDiff: right[f,i] = cos(x[f,i], x[f+iv, i+1])      (i < tpf-1)
//          down [f,i] = cos(x[f,i], x[f+iv, i+width])  (i < tpf-width)
// else -1. Output: [right | down], each frames*tpf f32.
//
// L1-throughput-bound (~60 B/cyc/SM effective LDG.128 ceiling; R2/R5 pinned
// at ~43 B/cyc regardless of occupancy). Volume reduction via FULL-VECTOR
// REGISTER CARRY chaining: right-target of (f,i) IS the anchor of (f+iv,i+1).
// A warp walks SEG=4 chain steps holding the whole anchor vector in registers
// (9 float4, rotated in place a[ch]=b); per step it streams only b (next
// anchor) and c (down-target) as 18 independent contiguous LDG.128. Anchor
// norm chains through the reduced n1. Volume = (1+2*SEG)/SEG = 2.25
// vectors/token (vs 3.0), full-vector bursts keep L2/DRAM locality intact.

#define EPSN 1e-8f
#define SEG 4

template <int NPL>  // D = NPL * 128 floats
__global__ void __launch_bounds__(128, 5) simdiff_carry_kernel(
    const float* __restrict__ x,
    const int* __restrict__ p_frames,
    const int* __restrict__ p_height,
    const int* __restrict__ p_width,
    const int* __restrict__ p_interval,
    float* __restrict__ out,
    int total)
{
    const int width  = *p_width;
    const int height = *p_height;
    const int frames = *p_frames;
    const int iv     = *p_interval;
    const int tpf    = width * height;

    // Chains step (f += iv, i += 1); starts: f0 < iv (any i0) or i0 == 0.
    const int nch_a = iv * tpf;
    const int nch_b = frames > iv ? frames - iv : 0;
    const int maxL  = min((frames + iv - 1) / iv, tpf);
    const int nsegper = (maxL + SEG - 1) / SEG;
    const long nseg = (long)(nch_a + nch_b) * nsegper;

    const int lane = threadIdx.x & 31;
    const long wstride = (long)gridDim.x * (blockDim.x >> 5);
    const long w0 = ((long)blockIdx.x * blockDim.x + threadIdx.x) >> 5;

    float* __restrict__ outR = out;
    float* __restrict__ outD = out + total;
    const float4* __restrict__ x4 = reinterpret_cast<const float4*>(x);
    const int vs   = NPL * 32;          // float4 per token vector
    const int dtok = iv * tpf + 1;      // chain step in tokens
    const int ctok = iv * tpf + width;  // down-target offset in tokens

    for (long g = w0; g < nseg; g += wstride) {
        const int chain = (int)(g / nsegper);
        const int seg   = (int)(g - (long)chain * nsegper);

        int f0, i0;
        if (chain < nch_a) { f0 = chain % iv; i0 = chain / iv; }
        else               { f0 = iv + (chain - nch_a); i0 = 0; }
        if (f0 >= frames || i0 >= tpf) continue;

        const int L  = min((frames - f0 + iv - 1) / iv, tpf - i0);
        const int k0 = seg * SEG;
        if (k0 >= L) continue;
        const int ns = min(SEG, L - k0);

        int fA = f0 + k0 * iv;
        int iA = i0 + k0;
        int t  = fA * tpf + iA;

        // Load the full anchor vector into registers; accumulate its norm.
        const float4* __restrict__ ap = x4 + (long)t * vs + lane;
        float4 a[NPL];
        float na = 0.0f;
#pragma unroll
        for (int ch = 0; ch < NPL; ch++) {
            const float4 v = ap[32 * ch];
            a[ch] = v;
            na = fmaf(v.x, v.x, na); na = fmaf(v.y, v.y, na);
            na = fmaf(v.z, v.z, na); na = fmaf(v.w, v.w, na);
        }
#pragma unroll
        for (int off = 16; off > 0; off >>= 1)
            na += __shfl_xor_sync(0xFFFFFFFFu, na, off);

        for (int k = 0; k < ns; k++) {
            const bool fv = (fA + iv) < frames;
            const bool vr = fv && (iA + 1 < tpf);
            const bool vd = fv && (iA < tpf - width);
            const int tb = t + dtok;
            const int tc = t + ctok;
            // Clamp invalid targets to the (in-bounds) current anchor; the
            // corresponding outputs are forced to -1 below. If vr is false
            // this is the chain's last step, so the bogus rotate is unused.
            const float4* __restrict__ bp =
                x4 + (long)(vr ? tb : t) * vs + lane;
            const float4* __restrict__ cp =
                x4 + (long)(vd ? tc : t) * vs + lane;

            float d1 = 0.f, n1 = 0.f, d2 = 0.f, n2 = 0.f;
#pragma unroll
            for (int ch = 0; ch < NPL; ch++) {
                const float4 b = bp[32 * ch];
                const float4 c = cp[32 * ch];
                const float4 av = a[ch];
                d1 = fmaf(av.x, b.x, d1); d1 = fmaf(av.y, b.y, d1);
                d1 = fmaf(av.z, b.z, d1); d1 = fmaf(av.w, b.w, d1);
                n1 = fmaf(b.x, b.x, n1);  n1 = fmaf(b.y, b.y, n1);
                n1 = fmaf(b.z, b.z, n1);  n1 = fmaf(b.w, b.w, n1);
                d2 = fmaf(av.x, c.x, d2); d2 = fmaf(av.y, c.y, d2);
                d2 = fmaf(av.z, c.z, d2); d2 = fmaf(av.w, c.w, d2);
                n2 = fmaf(c.x, c.x, n2);  n2 = fmaf(c.y, c.y, n2);
                n2 = fmaf(c.z, c.z, n2);  n2 = fmaf(c.w, c.w, n2);
                a[ch] = b;   // carry: target becomes next anchor
            }
#pragma unroll
            for (int off = 16; off > 0; off >>= 1) {
                d1 += __shfl_xor_sync(0xFFFFFFFFu, d1, off);
                n1 += __shfl_xor_sync(0xFFFFFFFFu, n1, off);
                d2 += __shfl_xor_sync(0xFFFFFFFFu, d2, off);
                n2 += __shfl_xor_sync(0xFFFFFFFFu, n2, off);
            }
            if (lane == 0) {
                const float nA = fmaxf(sqrtf(na), EPSN);
                outR[t] = vr ? d1 / (nA * fmaxf(sqrtf(n1), EPSN)) : -1.0f;
                outD[t] = vd ? d2 / (nA * fmaxf(sqrtf(n2), EPSN)) : -1.0f;
            }
            na = n1;            // reduced |b|^2 = next anchor's norm
            t = tb; fA += iv; iA += 1;
        }
    }
}

// Generic fallback for arbitrary D (scalar loads, one warp per token).
__global__ void __launch_bounds__(256) simdiff_generic_kernel(
    const float* __restrict__ x,
    const int* __restrict__ p_frames,
    const int* __restrict__ p_height,
    const int* __restrict__ p_width,
    const int* __restrict__ p_interval,
    float* __restrict__ out,
    int total, int D)
{
    const int gwarp = (blockIdx.x * blockDim.x + threadIdx.x) >> 5;
    const int lane  = threadIdx.x & 31;
    if (gwarp >= total) return;

    const int width    = *p_width;
    const int height   = *p_height;
    const int frames   = *p_frames;
    const int interval = *p_interval;
    const int tpf      = width * height;

    const int f = gwarp / tpf;
    const int i = gwarp - f * tpf;

    float* __restrict__ outR = out;
    float* __restrict__ outD = out + total;

    const bool vf = (f + interval) < frames;
    if (!vf) {
        if (lane == 0) { outR[gwarp] = -1.0f; outD[gwarp] = -1.0f; }
        return;
    }
    const bool vr = (i < tpf - 1);
    const bool vd = (i < tpf - width);

    const size_t bframe = (size_t)(f + interval) * tpf + i;
    const size_t i1 = vr ? (bframe + 1)     : bframe;
    const size_t i2 = vd ? (bframe + width) : bframe;

    const float* a = x + (size_t)gwarp * D;
    const float* b = x + i1 * D;
    const float* c = x + i2 * D;

    float na = 0.0f, d1 = 0.0f, n1 = 0.0f, d2 = 0.0f, n2 = 0.0f;
    for (int k = lane; k < D; k += 32) {
        float av = a[k], bv = b[k], cv = c[k];
        na = fmaf(av, av, na);
        d1 = fmaf(av, bv, d1); n1 = fmaf(bv, bv, n1);
        d2 = fmaf(av, cv, d2); n2 = fmaf(cv, cv, n2);
    }

#pragma unroll
    for (int off = 16; off > 0; off >>= 1) {
        na += __shfl_xor_sync(0xFFFFFFFFu, na, off);
        d1 += __shfl_xor_sync(0xFFFFFFFFu, d1, off);
        n1 += __shfl_xor_sync(0xFFFFFFFFu, n1, off);
        d2 += __shfl_xor_sync(0xFFFFFFFFu, d2, off);
        n2 += __shfl_xor_sync(0xFFFFFFFFu, n2, off);
    }

    if (lane == 0) {
        const float nA = fmaxf(sqrtf(na), EPSN);
        outR[gwarp] = vr ? d1 / (nA * fmaxf(sqrtf(n1), EPSN)) : -1.0f;
        outD[gwarp] = vd ? d2 / (nA * fmaxf(sqrtf(n2), EPSN)) : -1.0f;
    }
}

extern "C" void kernel_launch(void* const* d_in, const int* in_sizes, int n_in,
                              void* d_out, int out_size) {
    const float* x        = (const float*)d_in[0];
    const int* p_frames   = (const int*)d_in[1];
    const int* p_height   = (const int*)d_in[2];
    const int* p_width    = (const int*)d_in[3];
    const int* p_interval = (const int*)d_in[4];
    float* out = (float*)d_out;

    const int total = out_size / 2;            // frames * tpf
    const int D     = in_sizes[0] / total;     // hidden dim

    if (D == 1152 || D == 1024 || D == 1280) {
        // ~total/SEG segment-warps (+ chain-edge extras); 4 warps per CTA.
        // Grid-stride covers any remainder; surplus warps exit immediately.
        const int blocks = total / (4 * SEG) + 384;
        if (D == 1152) {
            simdiff_carry_kernel<9><<<blocks, 128>>>(
                x, p_frames, p_height, p_width, p_interval, out, total);
        } else if (D == 1024) {
            simdiff_carry_kernel<8><<<blocks, 128>>>(
                x, p_frames, p_height, p_width, p_interval, out, total);
        } else {
            simdiff_carry_kernel<10><<<blocks, 128>>>(
                x, p_frames, p_height, p_width, p_interval, out, total);
        }
    } else {
        const int blocks = (total + 7) / 8;
        simdiff_generic_kernel<<<blocks, 256>>>(
            x, p_frames, p_height, p_width, p_interval, out, total, D);
    }
}